// round 3
// baseline (speedup 1.0000x reference)
#include <cuda_runtime.h>
#include <cuda_fp16.h>
#include <cstdint>
#include <math_constants.h>

#define NT     65536
#define DIM    256
#define NE     1024
#define MCTA   128
#define MARGIN 2.5e-3f
#define CAND_CAP 12

// ---------------- smem layout (bytes) ----------------
#define SA32 0                 // z tile fp32, rotated float4 layout: [128][64] f4  (131072)
#define SA16 131072            // z tile fp16, row stride 264 halfs               (67584)
#define SBB  198656            // 2 B chunk buffers, each 128 codes x 40 halfs    (20480)
#define SE2  219136            // e2 all 1024 f32                                 (4096)
#define SZ2  223232            // row norms f32 [128]                             (512)
#define SRB  223744            // rowbest u64 [128]                               (1024)
#define SCN  224768            // cand count  [128] int                           (512)
#define SBI  225280            // best index  [128] int                           (512)
#define SCL  225792            // cand list [128][CAND_CAP] int (6144); aliased as loss red
#define SMEM_TOTAL 231936

#define A16_STRIDE_W 132       // words per A16 row (264 halfs)
#define B_STRIDE_W   20        // words per B row (40 halfs)
#define BBUF_BYTES   10240

__device__ double g_loss_acc;
__device__ float  g_e2[NE];
__device__ __align__(16) __half g_cb16[NE * DIM];

#define CP16(dst, src) asm volatile("cp.async.cg.shared.global [%0], [%1], 16;" :: "r"(dst), "l"(src) : "memory")
#define CP_COMMIT()    asm volatile("cp.async.commit_group;" ::: "memory")
#define CP_WAIT1()     asm volatile("cp.async.wait_group 1;" ::: "memory")

__device__ __forceinline__ uint32_t smem_u32(const void* p) {
    uint32_t a;
    asm("{ .reg .u64 t; cvta.to.shared.u64 t, %1; cvt.u32.u64 %0, t; }" : "=r"(a) : "l"(p));
    return a;
}

__device__ __forceinline__ void mma16816(float& c0, float& c1, float& c2, float& c3,
                                         uint32_t a0, uint32_t a1, uint32_t a2, uint32_t a3,
                                         uint32_t b0, uint32_t b1) {
    asm volatile("mma.sync.aligned.m16n8k16.row.col.f32.f16.f16.f32 "
                 "{%0,%1,%2,%3},{%4,%5,%6,%7},{%8,%9},{%0,%1,%2,%3};"
                 : "+f"(c0), "+f"(c1), "+f"(c2), "+f"(c3)
                 : "r"(a0), "r"(a1), "r"(a2), "r"(a3), "r"(b0), "r"(b1));
}

// rotated fp32 A element index (floats) for (row r, col k)
__device__ __forceinline__ int a32_idx(int r, int k) {
    return (r * 64 + (((k >> 2) + r) & 63)) * 4 + (k & 3);
}

// ---------------- prep: e2 (fp64) + cb->fp16 + zero loss ----------------
__global__ void vq_prep_kernel(const float* __restrict__ cb) {
    int tid = threadIdx.x, lane = tid & 31;
    if (blockIdx.x == 0 && tid == 0) g_loss_acc = 0.0;
    int gw = blockIdx.x * 8 + (tid >> 5);
    #pragma unroll
    for (int i = 0; i < 4; i++) {
        int c = gw * 4 + i;
        const float* row = cb + (size_t)c * DIM;
        double s = 0.0;
        #pragma unroll
        for (int j = 0; j < 8; j++) { double v = (double)row[lane + 32 * j]; s += v * v; }
        #pragma unroll
        for (int o = 16; o; o >>= 1) s += __shfl_xor_sync(0xffffffffu, s, o);
        if (lane == 0) g_e2[c] = (float)s;
    }
    // fp16 conversion: 262144 elems over 32 blocks x 256 thr = 32 each
    int base = blockIdx.x * 256 + tid;
    #pragma unroll
    for (int i = 0; i < 32; i++) {
        int idx = base + i * 8192;
        g_cb16[idx] = __float2half_rn(cb[idx]);
    }
}

// ---------------- main ----------------
__global__ __launch_bounds__(256, 1) void vq_main_kernel(
    const float* __restrict__ z,
    const float* __restrict__ cb,
    float* __restrict__ out)
{
    extern __shared__ char smem[];
    const uint32_t sb = smem_u32(smem);
    float*    a32  = (float*)(smem + SA32);
    uint32_t* a16w = (uint32_t*)(smem + SA16);
    float*    e2s  = (float*)(smem + SE2);
    float*    z2s  = (float*)(smem + SZ2);
    unsigned long long* rowbest = (unsigned long long*)(smem + SRB);
    int*      ccnt = (int*)(smem + SCN);
    int*      bi_s = (int*)(smem + SBI);
    int*      clist = (int*)(smem + SCL);

    const int tid  = threadIdx.x;
    const int wid  = tid >> 5;
    const int lane = tid & 31;
    const int q    = lane & 3;      // thread-in-group
    const int lq   = lane >> 2;     // group id
    const int m0   = blockIdx.x * MCTA;
    const int mb   = (wid & 3) * 32;     // warp row base
    const int nb   = (wid >> 2) * 64;    // warp col base within 128-ntile

    // ---- stage A: fp32 rotated + fp16 padded, coalesced ----
    #pragma unroll
    for (int i = 0; i < 32; i++) {
        int s = i * 256 + tid;
        int row = s >> 6, c4 = s & 63;
        float4 v = *(const float4*)(z + (size_t)(m0 + row) * DIM + c4 * 4);
        int f4 = row * 64 + ((c4 + row) & 63);
        ((float4*)a32)[f4] = v;
        __half2 h0 = __floats2half2_rn(v.x, v.y);
        __half2 h1 = __floats2half2_rn(v.z, v.w);
        uint32_t* dst = a16w + row * A16_STRIDE_W + c4 * 2;
        dst[0] = *(uint32_t*)&h0;
        dst[1] = *(uint32_t*)&h1;
    }
    // e2 table + init per-row state
    #pragma unroll
    for (int i = 0; i < 4; i++) e2s[i * 256 + tid] = g_e2[i * 256 + tid];
    if (tid < 128) {
        rowbest[tid] = 0x7F800000FFFFFFFFull;  // +inf dist, max idx
        ccnt[tid] = 0;
    }
    __syncthreads();

    // ---- row norms (fp64 exact, as R1) ----
    if (tid < 128) {
        double s = 0.0;
        #pragma unroll 8
        for (int k = 0; k < DIM; k++) {
            double v = (double)a32[a32_idx(tid, k)];
            s += v * v;
        }
        z2s[tid] = (float)s;
    }
    __syncthreads();

    // per-lane row ids + norms (4 row-slots: mt0 lo/hi, mt1 lo/hi)
    const int rs[4] = { mb + lq, mb + lq + 8, mb + 16 + lq, mb + 16 + lq + 24 - 16 };
    // (rs[3] = mb+24+lq)
    float z2r[4];
    #pragma unroll
    for (int i = 0; i < 4; i++) z2r[i] = z2s[rs[i]];

    // ---- B chunk loader: chunk c -> ntile c>>3, kchunk c&7, buffer c&1 ----
    auto load_chunk = [&](int c) {
        int nt = c >> 3, kc = c & 7;
        const __half* src0 = g_cb16 + (size_t)nt * 128 * DIM + kc * 32;
        uint32_t bbase = sb + SBB + (c & 1) * BBUF_BYTES;
        #pragma unroll
        for (int i = 0; i < 2; i++) {
            int s = i * 256 + tid;           // 512 16B segs
            int n = s >> 2, kseg = s & 3;
            CP16(bbase + n * 80 + kseg * 16, src0 + (size_t)n * DIM + kseg * 8);
        }
    };

    load_chunk(0); CP_COMMIT();
    load_chunk(1); CP_COMMIT();

    float acc[2][8][4];
    #pragma unroll
    for (int mt = 0; mt < 2; mt++)
        #pragma unroll
        for (int j = 0; j < 8; j++)
            #pragma unroll
            for (int e = 0; e < 4; e++) acc[mt][j][e] = 0.0f;

    for (int c = 0; c < 64; c++) {
        const int nt = c >> 3, kc = c & 7;
        CP_WAIT1();
        __syncthreads();

        const uint32_t* Bw = (const uint32_t*)(smem + SBB + (c & 1) * BBUF_BYTES);
        const int kc16 = kc * 16;
        #pragma unroll
        for (int ks = 0; ks < 2; ks++) {
            const int kw = kc16 + ks * 8 + q;
            uint32_t a[2][4];
            #pragma unroll
            for (int mt = 0; mt < 2; mt++) {
                int r = mb + 16 * mt + lq;
                a[mt][0] = a16w[r * A16_STRIDE_W + kw];
                a[mt][1] = a16w[(r + 8) * A16_STRIDE_W + kw];
                a[mt][2] = a16w[r * A16_STRIDE_W + kw + 4];
                a[mt][3] = a16w[(r + 8) * A16_STRIDE_W + kw + 4];
            }
            #pragma unroll
            for (int j = 0; j < 8; j++) {
                int nl = nb + 8 * j + lq;
                uint32_t b0 = Bw[nl * B_STRIDE_W + ks * 8 + q];
                uint32_t b1 = Bw[nl * B_STRIDE_W + ks * 8 + q + 4];
                mma16816(acc[0][j][0], acc[0][j][1], acc[0][j][2], acc[0][j][3],
                         a[0][0], a[0][1], a[0][2], a[0][3], b0, b1);
                mma16816(acc[1][j][0], acc[1][j][1], acc[1][j][2], acc[1][j][3],
                         a[1][0], a[1][1], a[1][2], a[1][3], b0, b1);
            }
        }

        if (kc == 7) {
            // ---- distance processing for ntile nt ----
            const int ntbase = nt * 128 + nb + 2 * q;
            #pragma unroll
            for (int slot = 0; slot < 4; slot++) {
                const int mt = slot >> 1, half = slot & 1;
                const int r = rs[slot];
                const float z2 = z2r[slot];
                float dmin = CUDART_INF_F; int darg = 0;
                #pragma unroll
                for (int j = 0; j < 8; j++) {
                    #pragma unroll
                    for (int e = 0; e < 2; e++) {
                        float dot = acc[mt][j][half * 2 + e];
                        int col = ntbase + 8 * j + e;
                        float dd = (z2 - 2.0f * dot) + e2s[col];
                        if (dd < dmin) { dmin = dd; darg = col; }
                    }
                }
                unsigned long long key =
                    ((unsigned long long)__float_as_uint(dmin) << 32) | (unsigned)darg;
                atomicMin(&rowbest[r], key);
                float eff = __uint_as_float((unsigned)(rowbest[r] >> 32)) + MARGIN;
                #pragma unroll
                for (int j = 0; j < 8; j++) {
                    #pragma unroll
                    for (int e = 0; e < 2; e++) {
                        float dot = acc[mt][j][half * 2 + e];
                        int col = ntbase + 8 * j + e;
                        float dd = (z2 - 2.0f * dot) + e2s[col];
                        if (dd <= eff) {
                            int p = atomicAdd(&ccnt[r], 1);
                            if (p < CAND_CAP) clist[r * CAND_CAP + p] = col;
                        }
                    }
                }
            }
            #pragma unroll
            for (int mt = 0; mt < 2; mt++)
                #pragma unroll
                for (int j = 0; j < 8; j++)
                    #pragma unroll
                    for (int e = 0; e < 4; e++) acc[mt][j][e] = 0.0f;
        }

        __syncthreads();
        if (c + 2 < 64) load_chunk(c + 2);
        CP_COMMIT();
    }

    __syncthreads();

    // ---- exact fp32 rescue (R1's serial FMA order) ----
    if (tid < 128) {
        const int r = tid;
        const float z2f = z2s[r];
        auto exact_dd = [&](int c) -> float {
            const float* cr = cb + (size_t)c * DIM;
            float a = 0.0f;
            #pragma unroll 8
            for (int k = 0; k < DIM; k++)
                a = fmaf(a32[a32_idx(r, k)], __ldg(cr + k), a);
            return (z2f - 2.0f * a) + e2s[c];
        };
        int bi = (int)(rowbest[r] & 0xffffffffu);
        float best = exact_dd(bi);
        int cnt = ccnt[r];
        if (cnt > CAND_CAP) {
            // overflow: full exact scan (pathological, ~never)
            for (int cidx = 0; cidx < NE; cidx++) {
                float d2 = exact_dd(cidx);
                if (d2 < best || (d2 == best && cidx < bi)) { best = d2; bi = cidx; }
            }
        } else {
            for (int p = 0; p < cnt; p++) {
                int cidx = clist[r * CAND_CAP + p];
                if (cidx == bi) continue;
                float d2 = exact_dd(cidx);
                if (d2 < best || (d2 == best && cidx < bi)) { best = d2; bi = cidx; }
            }
        }
        bi_s[r] = bi;
    }
    __syncthreads();

    // ---- epilogue: z_q_st (exact ST rounding), indices, loss ----
    double lsum = 0.0;
    for (int it = 0; it < 128; it++) {
        float zv = a32[a32_idx(it, tid)];
        float e  = __ldg(cb + (size_t)bi_s[it] * DIM + tid);
        float dq = e - zv;                  // fl(z_q - z)
        float o  = zv + dq;                 // fl(z + fl(z_q - z))
        out[(size_t)(m0 + it) * DIM + tid] = o;
        lsum += (double)dq * (double)dq;
    }
    if (tid < 128)
        out[(size_t)NT * DIM + 1 + m0 + tid] = (float)bi_s[tid];

    __syncthreads();                // clist no longer needed -> reuse as reduction
    double* red = (double*)(smem + SCL);
    red[tid] = lsum;
    __syncthreads();
    #pragma unroll
    for (int s = 128; s > 0; s >>= 1) {
        if (tid < s) red[tid] += red[tid + s];
        __syncthreads();
    }
    if (tid == 0) atomicAdd(&g_loss_acc, red[0]);
}

__global__ void vq_loss_kernel(float* __restrict__ out) {
    out[(size_t)NT * DIM] = (float)(1.25 * g_loss_acc / ((double)NT * (double)DIM));
}

// ---------------------------------------------------------------------------
extern "C" void kernel_launch(void* const* d_in, const int* in_sizes, int n_in,
                              void* d_out, int out_size) {
    const float *z, *cb;
    if (in_sizes[0] == NT * DIM) { z = (const float*)d_in[0]; cb = (const float*)d_in[1]; }
    else                         { z = (const float*)d_in[1]; cb = (const float*)d_in[0]; }
    float* out = (float*)d_out;

    cudaFuncSetAttribute(vq_main_kernel,
                         cudaFuncAttributeMaxDynamicSharedMemorySize, SMEM_TOTAL);

    vq_prep_kernel<<<32, 256>>>(cb);
    vq_main_kernel<<<NT / MCTA, 256, SMEM_TOTAL>>>(z, cb, out);
    vq_loss_kernel<<<1, 1>>>(out);
}

// round 5
// speedup vs baseline: 10.6886x; 10.6886x over previous
#include <cuda_runtime.h>
#include <cuda_fp16.h>
#include <cstdint>
#include <math_constants.h>

#define NT     65536
#define DIM    256
#define NE     1024
#define MCTA   64
#define MQ     32            // capture window in q-units (3.05e-5 each)
#define CCAP   16

// ---------------- smem layout (bytes) ----------------
#define SA16  0              // z tile fp16: 64 rows x 264 halfs (132 words)    33792
#define SBB   33792          // 2 B chunk buffers x 10240                       20480
#define SQD   54272          // qd: 64 rows x 516 u32 words (s16 pairs)        132096
#define SE2   186368         // e2 all 1024 f32                                  4096
#define SZ2   190464         // row norms f32 [64]                                256
#define SCN   190720         // cand count [64] int                               256
#define SMINQ 190976         // min q per row [64] int                            256
#define SBI   191232         // best index [64] int                               256
#define SCL   191488         // cand list [64][CCAP] int                         4096
#define SRED  195584         // loss reduction [256] double                      2048
#define SMEM_TOTAL 197632

#define A16_STRIDE_W 132
#define B_STRIDE_W   20
#define BBUF_BYTES   10240
#define QD_STRIDE_W  516     // 512 data words + 4 pad (conflict-free writes)

__device__ double g_loss_acc;
__device__ float  g_e2[NE];
__device__ __align__(16) __half g_cb16[NE * DIM];

#define CP16(dst, src) asm volatile("cp.async.cg.shared.global [%0], [%1], 16;" :: "r"(dst), "l"(src) : "memory")
#define CP_COMMIT()    asm volatile("cp.async.commit_group;" ::: "memory")
#define CP_WAIT1()     asm volatile("cp.async.wait_group 1;" ::: "memory")
#define CP_WAIT0()     asm volatile("cp.async.wait_group 0;" ::: "memory")

__device__ __forceinline__ uint32_t smem_u32(const void* p) {
    uint32_t a;
    asm("{ .reg .u64 t; cvta.to.shared.u64 t, %1; cvt.u32.u64 %0, t; }" : "=r"(a) : "l"(p));
    return a;
}

__device__ __forceinline__ void mma16816(float& c0, float& c1, float& c2, float& c3,
                                         uint32_t a0, uint32_t a1, uint32_t a2, uint32_t a3,
                                         uint32_t b0, uint32_t b1) {
    asm volatile("mma.sync.aligned.m16n8k16.row.col.f32.f16.f16.f32 "
                 "{%0,%1,%2,%3},{%4,%5,%6,%7},{%8,%9},{%0,%1,%2,%3};"
                 : "+f"(c0), "+f"(c1), "+f"(c2), "+f"(c3)
                 : "r"(a0), "r"(a1), "r"(a2), "r"(a3), "r"(b0), "r"(b1));
}

// ---------------- prep: e2 (fp64) + cb->fp16 + zero loss ----------------
__global__ void vq_prep_kernel(const float* __restrict__ cb) {
    int tid = threadIdx.x, lane = tid & 31;
    if (blockIdx.x == 0 && tid == 0) g_loss_acc = 0.0;
    int gw = blockIdx.x * 8 + (tid >> 5);
    #pragma unroll
    for (int i = 0; i < 4; i++) {
        int c = gw * 4 + i;
        const float* row = cb + (size_t)c * DIM;
        double s = 0.0;
        #pragma unroll
        for (int j = 0; j < 8; j++) { double v = (double)row[lane + 32 * j]; s += v * v; }
        #pragma unroll
        for (int o = 16; o; o >>= 1) s += __shfl_xor_sync(0xffffffffu, s, o);
        if (lane == 0) g_e2[c] = (float)s;
    }
    int base = blockIdx.x * 256 + tid;
    #pragma unroll
    for (int i = 0; i < 32; i++) {
        int idx = base + i * 8192;
        g_cb16[idx] = __float2half_rn(cb[idx]);
    }
}

// ---------------- main ----------------
__global__ __launch_bounds__(256, 1) void vq_main_kernel(
    const float* __restrict__ z,
    const float* __restrict__ cb,
    float* __restrict__ out)
{
    extern __shared__ char smem[];
    const uint32_t sbu = smem_u32(smem);
    uint32_t* a16w  = (uint32_t*)(smem + SA16);
    uint32_t* qd    = (uint32_t*)(smem + SQD);
    float*    e2s   = (float*)(smem + SE2);
    float*    z2s   = (float*)(smem + SZ2);
    int*      ccnt  = (int*)(smem + SCN);
    int*      minqs = (int*)(smem + SMINQ);
    int*      bi_s  = (int*)(smem + SBI);
    int*      clist = (int*)(smem + SCL);

    const int tid  = threadIdx.x;
    const int wid  = tid >> 5;
    const int lane = tid & 31;
    const int q    = lane & 3;
    const int lq   = lane >> 2;
    const int m0   = blockIdx.x * MCTA;
    const int rw   = (wid & 3) * 16;     // warp row base (16 rows)
    const int nb2  = (wid >> 2);         // warp col half of ntile (0/1)

    // ---- stage A fp16 (padded), e2 table, init ----
    #pragma unroll
    for (int i = 0; i < 16; i++) {
        int s = i * 256 + tid;
        int row = s >> 6, c4 = s & 63;
        float4 v = *(const float4*)(z + (size_t)(m0 + row) * DIM + c4 * 4);
        __half2 h0 = __floats2half2_rn(v.x, v.y);
        __half2 h1 = __floats2half2_rn(v.z, v.w);
        uint32_t* dst = a16w + row * A16_STRIDE_W + c4 * 2;
        dst[0] = *(uint32_t*)&h0;
        dst[1] = *(uint32_t*)&h1;
    }
    #pragma unroll
    for (int i = 0; i < 4; i++) e2s[i * 256 + tid] = g_e2[i * 256 + tid];
    if (tid < MCTA) ccnt[tid] = 0;

    // ---- row norms (fp64 serial from global, exact as R1) ----
    if (tid < MCTA) {
        const float* zr = z + (size_t)(m0 + tid) * DIM;
        double s = 0.0;
        #pragma unroll 8
        for (int k = 0; k < DIM; k++) { double v = (double)zr[k]; s += v * v; }
        z2s[tid] = (float)s;
    }
    __syncthreads();

    // ---- B chunk loader: chunk c -> ntile c>>3, kchunk c&7, buffer c&1 ----
    auto load_chunk = [&](int c) {
        int nt = c >> 3, kc = c & 7;
        const __half* src0 = g_cb16 + (size_t)nt * 128 * DIM + kc * 32;
        uint32_t bbase = sbu + SBB + (c & 1) * BBUF_BYTES;
        #pragma unroll
        for (int i = 0; i < 2; i++) {
            int s = i * 256 + tid;           // 512 16B segs
            int n = s >> 2, kseg = s & 3;
            CP16(bbase + n * 80 + kseg * 16, src0 + (size_t)n * DIM + kseg * 8);
        }
    };
    load_chunk(0); CP_COMMIT();
    load_chunk(1); CP_COMMIT();

    float acc[8][4];
    #pragma unroll
    for (int j = 0; j < 8; j++)
        #pragma unroll
        for (int e = 0; e < 4; e++) acc[j][e] = 0.0f;

    const int r0 = rw + lq;
    for (int c = 0; c < 64; c++) {
        const int nt = c >> 3, kc = c & 7;
        CP_WAIT1();
        __syncthreads();

        const uint32_t* Bw = (const uint32_t*)(smem + SBB + (c & 1) * BBUF_BYTES);
        #pragma unroll
        for (int ks = 0; ks < 2; ks++) {
            const int kw = kc * 16 + ks * 8 + q;
            uint32_t a0 = a16w[r0 * A16_STRIDE_W + kw];
            uint32_t a1 = a16w[(r0 + 8) * A16_STRIDE_W + kw];
            uint32_t a2 = a16w[r0 * A16_STRIDE_W + kw + 4];
            uint32_t a3 = a16w[(r0 + 8) * A16_STRIDE_W + kw + 4];
            #pragma unroll
            for (int j = 0; j < 8; j++) {
                int nl = nb2 * 64 + 8 * j + lq;
                uint32_t b0 = Bw[nl * B_STRIDE_W + ks * 8 + q];
                uint32_t b1 = Bw[nl * B_STRIDE_W + ks * 8 + q + 4];
                mma16816(acc[j][0], acc[j][1], acc[j][2], acc[j][3],
                         a0, a1, a2, a3, b0, b1);
            }
        }

        if (kc == 7) {
            // q16 = round((e2 - 2*dot) * 2^15)  (z2 omitted: constant per row)
            #pragma unroll
            for (int j = 0; j < 8; j++) {
                int col0 = nt * 128 + nb2 * 64 + 8 * j + 2 * q;
                float e20 = e2s[col0], e21 = e2s[col0 + 1];
                int wIdx = (col0 >> 1);   // = nt*64 + nb2*32 + 4j + q
                #pragma unroll
                for (int h = 0; h < 2; h++) {
                    float s0 = e20 - 2.0f * acc[j][h * 2 + 0];
                    float s1 = e21 - 2.0f * acc[j][h * 2 + 1];
                    int q0 = __float2int_rn(s0 * 32768.0f);
                    int q1 = __float2int_rn(s1 * 32768.0f);
                    q0 = max(-32767, min(32767, q0));
                    q1 = max(-32767, min(32767, q1));
                    qd[(r0 + 8 * h) * QD_STRIDE_W + wIdx] =
                        ((uint32_t)(q1 & 0xffff) << 16) | (uint32_t)(q0 & 0xffff);
                    acc[j][h * 2 + 0] = 0.0f;
                    acc[j][h * 2 + 1] = 0.0f;
                }
            }
        }

        __syncthreads();
        if (c + 2 < 64) load_chunk(c + 2);
        CP_COMMIT();
    }
    CP_WAIT0();
    __syncthreads();

    // ---- per-row FINAL min + capture (warp w owns rows 8w..8w+7) ----
    for (int rr = 0; rr < 8; rr++) {
        int r = wid * 8 + rr;
        const uint32_t* row = qd + r * QD_STRIDE_W;
        uint32_t v[16];
        int mn = 0x7fffffff;
        #pragma unroll
        for (int i = 0; i < 16; i++) {
            v[i] = row[lane + 32 * i];
            int a = (int)(short)(v[i] & 0xffff);
            int b = (int)(short)(v[i] >> 16);
            mn = min(mn, min(a, b));
        }
        #pragma unroll
        for (int o = 16; o; o >>= 1) mn = min(mn, __shfl_xor_sync(0xffffffffu, mn, o));
        int thr = mn + MQ;
        #pragma unroll
        for (int i = 0; i < 16; i++) {
            int a = (int)(short)(v[i] & 0xffff);
            int b = (int)(short)(v[i] >> 16);
            int colw = lane + 32 * i;
            if (a <= thr) {
                int p = atomicAdd(&ccnt[r], 1);
                if (p < CCAP) clist[r * CCAP + p] = 2 * colw;
            }
            if (b <= thr) {
                int p = atomicAdd(&ccnt[r], 1);
                if (p < CCAP) clist[r * CCAP + p] = 2 * colw + 1;
            }
        }
        if (lane == 0) minqs[r] = mn;
    }
    __syncthreads();

    // ---- exact fp32 rescue (R1's serial FMA order) ----
    if (tid < MCTA) {
        const int r = tid;
        const float z2f = z2s[r];
        const float* zr = z + (size_t)(m0 + r) * DIM;
        auto exact_dd = [&](int cidx) -> float {
            const float* cr = cb + (size_t)cidx * DIM;
            float a = 0.0f;
            #pragma unroll 8
            for (int k = 0; k < DIM; k++)
                a = fmaf(__ldg(zr + k), __ldg(cr + k), a);
            return (z2f - 2.0f * a) + e2s[cidx];
        };
        float best = CUDART_INF_F; int bi = 0x7fffffff;
        int cnt = ccnt[r];
        if (cnt <= CCAP) {
            for (int p = 0; p < cnt; p++) {
                int cidx = clist[r * CCAP + p];
                float d2 = exact_dd(cidx);
                if (d2 < best || (d2 == best && cidx < bi)) { best = d2; bi = cidx; }
            }
        } else {
            // bounded fallback: re-scan stored q row, exact-check q <= thr only
            int thr = minqs[r] + MQ;
            const uint32_t* row = qd + r * QD_STRIDE_W;
            for (int w = 0; w < 512; w++) {
                uint32_t vv = row[w];
                int a = (int)(short)(vv & 0xffff);
                int b = (int)(short)(vv >> 16);
                if (a <= thr) {
                    int cidx = 2 * w;
                    float d2 = exact_dd(cidx);
                    if (d2 < best || (d2 == best && cidx < bi)) { best = d2; bi = cidx; }
                }
                if (b <= thr) {
                    int cidx = 2 * w + 1;
                    float d2 = exact_dd(cidx);
                    if (d2 < best || (d2 == best && cidx < bi)) { best = d2; bi = cidx; }
                }
            }
        }
        bi_s[r] = bi;
    }
    __syncthreads();

    // ---- epilogue: z_q_st (exact ST rounding), indices, loss ----
    double lsum = 0.0;
    #pragma unroll 4
    for (int it = 0; it < MCTA; it++) {
        float zv = z[(size_t)(m0 + it) * DIM + tid];
        float e  = __ldg(cb + (size_t)bi_s[it] * DIM + tid);
        float dq = e - zv;                  // fl(z_q - z)
        float o  = zv + dq;                 // fl(z + fl(z_q - z))
        out[(size_t)(m0 + it) * DIM + tid] = o;
        lsum += (double)dq * (double)dq;
    }
    if (tid < MCTA)
        out[(size_t)NT * DIM + 1 + m0 + tid] = (float)bi_s[tid];

    double* red = (double*)(smem + SRED);
    red[tid] = lsum;
    __syncthreads();
    #pragma unroll
    for (int s = 128; s > 0; s >>= 1) {
        if (tid < s) red[tid] += red[tid + s];
        __syncthreads();
    }
    if (tid == 0) atomicAdd(&g_loss_acc, red[0]);
}

__global__ void vq_loss_kernel(float* __restrict__ out) {
    out[(size_t)NT * DIM] = (float)(1.25 * g_loss_acc / ((double)NT * (double)DIM));
}

// ---------------------------------------------------------------------------
extern "C" void kernel_launch(void* const* d_in, const int* in_sizes, int n_in,
                              void* d_out, int out_size) {
    const float *z, *cb;
    if (in_sizes[0] == NT * DIM) { z = (const float*)d_in[0]; cb = (const float*)d_in[1]; }
    else                         { z = (const float*)d_in[1]; cb = (const float*)d_in[0]; }
    float* out = (float*)d_out;

    cudaFuncSetAttribute(vq_main_kernel,
                         cudaFuncAttributeMaxDynamicSharedMemorySize, SMEM_TOTAL);

    vq_prep_kernel<<<32, 256>>>(cb);
    vq_main_kernel<<<NT / MCTA, 256, SMEM_TOTAL>>>(z, cb, out);
    vq_loss_kernel<<<1, 1>>>(out);
}

// round 6
// speedup vs baseline: 12.8766x; 1.2047x over previous
#include <cuda_runtime.h>
#include <cuda_fp16.h>
#include <cstdint>
#include <math_constants.h>

#define NT     65536
#define DIM    256
#define NE     1024
#define MCTA   64
#define MQ     32            // capture window in q-units (3.05e-5 each)
#define CCAP   16

// ---------------- smem layout (bytes) ----------------
#define SA16  0              // z tile fp16: 64 rows x 136 words (pair-permuted)  34816
#define SBB   34816          // 2 B chunk buffers x 20480 (k64 chunks)            40960
#define SQD   75776          // qd: 64 rows x 516 u32 words (s16 pairs)          132096
#define SE2   207872         // e2 all 1024 f32                                    4096
#define SZ2   211968         // row norms f32 [64]                                  256
#define SCN   212224         // cand count [64] int                                 256
#define SMINQ 212480         // min q per row [64] int                              256
#define SBI   212736         // best index [64] int                                 256
#define SCL   212992         // cand list [64][CCAP] int                           4096
#define SRED  217088         // loss reduction [256] double                        2048
#define SMEM_TOTAL 219136

#define A_STRIDE_W   136     // words per A row (128 data + 8 pad; mod32=8 -> conflict-free LDS.64)
#define B_STRIDE_W   40      // words per B code row in chunk (32 data + 8 pad)
#define BBUF_BYTES   20480
#define QD_STRIDE_W  516

__device__ double g_loss_acc;
__device__ float  g_e2[NE];
// pair-permuted fp16 codebook: per code 256 halfs; within each 16-half group G:
// new half[4q..4q+3] = old halves (2q, 2q+1, 2q+8, 2q+9)
__device__ __align__(16) __half g_cb16[NE * DIM];

#define CP16(dst, src) asm volatile("cp.async.cg.shared.global [%0], [%1], 16;" :: "r"(dst), "l"(src) : "memory")
#define CP_COMMIT()    asm volatile("cp.async.commit_group;" ::: "memory")
#define CP_WAIT1()     asm volatile("cp.async.wait_group 1;" ::: "memory")
#define CP_WAIT0()     asm volatile("cp.async.wait_group 0;" ::: "memory")

__device__ __forceinline__ uint32_t smem_u32(const void* p) {
    uint32_t a;
    asm("{ .reg .u64 t; cvta.to.shared.u64 t, %1; cvt.u32.u64 %0, t; }" : "=r"(a) : "l"(p));
    return a;
}

__device__ __forceinline__ void mma16816(float& c0, float& c1, float& c2, float& c3,
                                         uint32_t a0, uint32_t a1, uint32_t a2, uint32_t a3,
                                         uint32_t b0, uint32_t b1) {
    asm volatile("mma.sync.aligned.m16n8k16.row.col.f32.f16.f16.f32 "
                 "{%0,%1,%2,%3},{%4,%5,%6,%7},{%8,%9},{%0,%1,%2,%3};"
                 : "+f"(c0), "+f"(c1), "+f"(c2), "+f"(c3)
                 : "r"(a0), "r"(a1), "r"(a2), "r"(a3), "r"(b0), "r"(b1));
}

// ---------------- prep: e2 (fp64) + cb->fp16 pair-permuted + zero loss ----------------
__global__ void vq_prep_kernel(const float* __restrict__ cb) {
    int tid = threadIdx.x, lane = tid & 31;
    if (blockIdx.x == 0 && tid == 0) g_loss_acc = 0.0;
    int gw = blockIdx.x * 8 + (tid >> 5);
    #pragma unroll
    for (int i = 0; i < 4; i++) {
        int c = gw * 4 + i;
        const float* row = cb + (size_t)c * DIM;
        double s = 0.0;
        #pragma unroll
        for (int j = 0; j < 8; j++) { double v = (double)row[lane + 32 * j]; s += v * v; }
        #pragma unroll
        for (int o = 16; o; o >>= 1) s += __shfl_xor_sync(0xffffffffu, s, o);
        if (lane == 0) g_e2[c] = (float)s;
    }
    // permuted fp16 conversion: 131072 output words over 8192 threads -> 16 each
    uint32_t* out16 = (uint32_t*)g_cb16;
    int base = blockIdx.x * 256 + tid;
    #pragma unroll
    for (int i = 0; i < 16; i++) {
        int w = base + i * 8192;            // output word index
        int n = w >> 7, m = w & 127;        // code, word-in-code
        int G = m >> 3, p = m & 7;
        int q = p >> 1, hi = p & 1;
        int k0 = G * 16 + (hi ? (2 * q + 8) : (2 * q));
        __half2 h = __floats2half2_rn(cb[(size_t)n * DIM + k0], cb[(size_t)n * DIM + k0 + 1]);
        out16[w] = *(uint32_t*)&h;
    }
}

// ---------------- main ----------------
__global__ __launch_bounds__(256, 1) void vq_main_kernel(
    const float* __restrict__ z,
    const float* __restrict__ cb,
    float* __restrict__ out)
{
    extern __shared__ char smem[];
    const uint32_t sbu = smem_u32(smem);
    uint32_t* a16w  = (uint32_t*)(smem + SA16);
    uint32_t* qd    = (uint32_t*)(smem + SQD);
    float*    e2s   = (float*)(smem + SE2);
    float*    z2s   = (float*)(smem + SZ2);
    int*      ccnt  = (int*)(smem + SCN);
    int*      minqs = (int*)(smem + SMINQ);
    int*      bi_s  = (int*)(smem + SBI);
    int*      clist = (int*)(smem + SCL);

    const int tid  = threadIdx.x;
    const int wid  = tid >> 5;
    const int lane = tid & 31;
    const int q    = lane & 3;
    const int lq   = lane >> 2;
    const int m0   = blockIdx.x * MCTA;
    const int rw   = (wid & 3) * 16;     // warp row base (16 rows)
    const int nb2  = (wid >> 2);         // warp col half of ntile (0/1)

    // ---- stage A fp16 pair-permuted, e2 table, init ----
    #pragma unroll
    for (int i = 0; i < 16; i++) {
        int s = i * 256 + tid;
        int row = s >> 6, c4 = s & 63;
        float4 v = *(const float4*)(z + (size_t)(m0 + row) * DIM + c4 * 4);
        __half2 h0 = __floats2half2_rn(v.x, v.y);
        __half2 h1 = __floats2half2_rn(v.z, v.w);
        int w0 = 2 * c4, w1 = w0 + 1;
        int g0 = w0 >> 3, p0 = w0 & 7;
        int n0 = g0 * 8 + (p0 < 4 ? 2 * p0 : 2 * (p0 - 4) + 1);
        int g1 = w1 >> 3, p1 = w1 & 7;
        int n1 = g1 * 8 + (p1 < 4 ? 2 * p1 : 2 * (p1 - 4) + 1);
        a16w[row * A_STRIDE_W + n0] = *(uint32_t*)&h0;
        a16w[row * A_STRIDE_W + n1] = *(uint32_t*)&h1;
    }
    #pragma unroll
    for (int i = 0; i < 4; i++) e2s[i * 256 + tid] = g_e2[i * 256 + tid];
    if (tid < MCTA) ccnt[tid] = 0;

    // ---- row norms: warp-parallel fp64 (warp w owns rows 8w..8w+7) ----
    #pragma unroll
    for (int rr = 0; rr < 8; rr++) {
        int r = wid * 8 + rr;
        const float* zr = z + (size_t)(m0 + r) * DIM;
        double s = 0.0;
        #pragma unroll
        for (int i = 0; i < 8; i++) { double v = (double)zr[lane + 32 * i]; s += v * v; }
        #pragma unroll
        for (int o = 16; o; o >>= 1) s += __shfl_xor_sync(0xffffffffu, s, o);
        if (lane == 0) z2s[r] = (float)s;
    }
    __syncthreads();

    // ---- B chunk loader: chunk c -> ntile c>>2, k64-chunk c&3, buffer c&1 ----
    auto load_chunk = [&](int c) {
        int nt = c >> 2, kc = c & 3;
        const char* src0 = (const char*)g_cb16 + (size_t)nt * 128 * 512 + kc * 128;
        uint32_t bbase = sbu + SBB + (c & 1) * BBUF_BYTES;
        #pragma unroll
        for (int i = 0; i < 4; i++) {
            int s = i * 256 + tid;          // 1024 16B segs
            int n = s >> 3, seg = s & 7;
            CP16(bbase + n * 160 + seg * 16, src0 + (size_t)n * 512 + seg * 16);
        }
    };
    load_chunk(0); CP_COMMIT();
    load_chunk(1); CP_COMMIT();

    float acc[8][4];
    #pragma unroll
    for (int j = 0; j < 8; j++)
        #pragma unroll
        for (int e = 0; e < 4; e++) acc[j][e] = 0.0f;

    const int r0 = rw + lq;
    for (int c = 0; c < 32; c++) {
        const int nt = c >> 2, kc = c & 3;
        CP_WAIT1();
        __syncthreads();

        const uint32_t* Bw = (const uint32_t*)(smem + SBB + (c & 1) * BBUF_BYTES);
        #pragma unroll
        for (int g = 0; g < 4; g++) {
            const int aw = (kc * 4 + g) * 8 + 2 * q;
            uint2 A0 = *(const uint2*)(a16w + r0 * A_STRIDE_W + aw);
            uint2 A1 = *(const uint2*)(a16w + (r0 + 8) * A_STRIDE_W + aw);
            #pragma unroll
            for (int j = 0; j < 8; j++) {
                int nl = nb2 * 64 + 8 * j + lq;
                uint2 B0 = *(const uint2*)(Bw + nl * B_STRIDE_W + g * 8 + 2 * q);
                mma16816(acc[j][0], acc[j][1], acc[j][2], acc[j][3],
                         A0.x, A1.x, A0.y, A1.y, B0.x, B0.y);
            }
        }

        if (kc == 3) {
            // q16 = round((e2 - 2*dot) * 2^15)  (z2 omitted: constant per row)
            #pragma unroll
            for (int j = 0; j < 8; j++) {
                int col0 = nt * 128 + nb2 * 64 + 8 * j + 2 * q;
                float e20 = e2s[col0], e21 = e2s[col0 + 1];
                int wIdx = (col0 >> 1);
                #pragma unroll
                for (int h = 0; h < 2; h++) {
                    float s0 = e20 - 2.0f * acc[j][h * 2 + 0];
                    float s1 = e21 - 2.0f * acc[j][h * 2 + 1];
                    int q0 = __float2int_rn(s0 * 32768.0f);
                    int q1 = __float2int_rn(s1 * 32768.0f);
                    q0 = max(-32767, min(32767, q0));
                    q1 = max(-32767, min(32767, q1));
                    qd[(r0 + 8 * h) * QD_STRIDE_W + wIdx] =
                        ((uint32_t)(q1 & 0xffff) << 16) | (uint32_t)(q0 & 0xffff);
                    acc[j][h * 2 + 0] = 0.0f;
                    acc[j][h * 2 + 1] = 0.0f;
                }
            }
        }

        __syncthreads();
        if (c + 2 < 32) load_chunk(c + 2);
        CP_COMMIT();
    }
    CP_WAIT0();
    __syncthreads();

    // ---- per-row FINAL min + capture (warp w owns rows 8w..8w+7) ----
    for (int rr = 0; rr < 8; rr++) {
        int r = wid * 8 + rr;
        const uint32_t* row = qd + r * QD_STRIDE_W;
        uint32_t v[16];
        int mn = 0x7fffffff;
        #pragma unroll
        for (int i = 0; i < 16; i++) {
            v[i] = row[lane + 32 * i];
            int a = (int)(short)(v[i] & 0xffff);
            int b = (int)(short)(v[i] >> 16);
            mn = min(mn, min(a, b));
        }
        #pragma unroll
        for (int o = 16; o; o >>= 1) mn = min(mn, __shfl_xor_sync(0xffffffffu, mn, o));
        int thr = mn + MQ;
        #pragma unroll
        for (int i = 0; i < 16; i++) {
            int a = (int)(short)(v[i] & 0xffff);
            int b = (int)(short)(v[i] >> 16);
            int colw = lane + 32 * i;
            if (a <= thr) {
                int p = atomicAdd(&ccnt[r], 1);
                if (p < CCAP) clist[r * CCAP + p] = 2 * colw;
            }
            if (b <= thr) {
                int p = atomicAdd(&ccnt[r], 1);
                if (p < CCAP) clist[r * CCAP + p] = 2 * colw + 1;
            }
        }
        if (lane == 0) minqs[r] = mn;
    }
    __syncthreads();

    // ---- exact fp32 rescue (R1's serial FMA order) ----
    if (tid < MCTA) {
        const int r = tid;
        const float z2f = z2s[r];
        const float* zr = z + (size_t)(m0 + r) * DIM;
        auto exact_dd = [&](int cidx) -> float {
            const float* cr = cb + (size_t)cidx * DIM;
            float a = 0.0f;
            #pragma unroll 8
            for (int k = 0; k < DIM; k++)
                a = fmaf(__ldg(zr + k), __ldg(cr + k), a);
            return (z2f - 2.0f * a) + e2s[cidx];
        };
        float best = CUDART_INF_F; int bi = 0x7fffffff;
        int cnt = ccnt[r];
        if (cnt <= CCAP) {
            for (int p = 0; p < cnt; p++) {
                int cidx = clist[r * CCAP + p];
                float d2 = exact_dd(cidx);
                if (d2 < best || (d2 == best && cidx < bi)) { best = d2; bi = cidx; }
            }
        } else {
            // bounded fallback: re-scan stored q row, exact-check q <= thr only
            int thr = minqs[r] + MQ;
            const uint32_t* row = qd + r * QD_STRIDE_W;
            for (int w = 0; w < 512; w++) {
                uint32_t vv = row[w];
                int a = (int)(short)(vv & 0xffff);
                int b = (int)(short)(vv >> 16);
                if (a <= thr) {
                    int cidx = 2 * w;
                    float d2 = exact_dd(cidx);
                    if (d2 < best || (d2 == best && cidx < bi)) { best = d2; bi = cidx; }
                }
                if (b <= thr) {
                    int cidx = 2 * w + 1;
                    float d2 = exact_dd(cidx);
                    if (d2 < best || (d2 == best && cidx < bi)) { best = d2; bi = cidx; }
                }
            }
        }
        bi_s[r] = bi;
    }
    __syncthreads();

    // ---- epilogue: z_q_st (exact ST rounding), indices, loss (fp32 partials) ----
    float lacc = 0.0f;
    #pragma unroll 4
    for (int it = 0; it < MCTA; it++) {
        float zv = z[(size_t)(m0 + it) * DIM + tid];
        float e  = __ldg(cb + (size_t)bi_s[it] * DIM + tid);
        float dq = e - zv;                  // fl(z_q - z)
        float o  = zv + dq;                 // fl(z + fl(z_q - z))
        out[(size_t)(m0 + it) * DIM + tid] = o;
        lacc = fmaf(dq, dq, lacc);
    }
    if (tid < MCTA)
        out[(size_t)NT * DIM + 1 + m0 + tid] = (float)bi_s[tid];

    double* red = (double*)(smem + SRED);
    red[tid] = (double)lacc;
    __syncthreads();
    #pragma unroll
    for (int s = 128; s > 0; s >>= 1) {
        if (tid < s) red[tid] += red[tid + s];
        __syncthreads();
    }
    if (tid == 0) atomicAdd(&g_loss_acc, red[0]);
}

__global__ void vq_loss_kernel(float* __restrict__ out) {
    out[(size_t)NT * DIM] = (float)(1.25 * g_loss_acc / ((double)NT * (double)DIM));
}

// ---------------------------------------------------------------------------
extern "C" void kernel_launch(void* const* d_in, const int* in_sizes, int n_in,
                              void* d_out, int out_size) {
    const float *z, *cb;
    if (in_sizes[0] == NT * DIM) { z = (const float*)d_in[0]; cb = (const float*)d_in[1]; }
    else                         { z = (const float*)d_in[1]; cb = (const float*)d_in[0]; }
    float* out = (float*)d_out;

    cudaFuncSetAttribute(vq_main_kernel,
                         cudaFuncAttributeMaxDynamicSharedMemorySize, SMEM_TOTAL);

    vq_prep_kernel<<<32, 256>>>(cb);
    vq_main_kernel<<<NT / MCTA, 256, SMEM_TOTAL>>>(z, cb, out);
    vq_loss_kernel<<<1, 1>>>(out);
}